// round 2
// baseline (speedup 1.0000x reference)
#include <cuda_runtime.h>

#define N_NODES 8192
#define N_EDGES 262144
#define D 512
#define MW 256   // 8192 bits / 32 = 256 mask words per row

// Scratch (device globals; no allocations allowed)
__device__ unsigned int g_mask[N_NODES * MW];          // 8 MB adjacency bitmask
__device__ float        g_dinv[N_NODES];               // D^{-1/2}
__device__ __align__(16) float g_h[N_NODES * D];       // H' = dinv[m] * (X @ W)[m]
__device__ int          g_is64;                        // edge_index dtype flag

// ---------------------------------------------------------------------------
// 0) detect edge_index dtype: int64 values < 8192 have all-zero high words
//    at odd int32 positions; int32 random data almost surely doesn't.
// ---------------------------------------------------------------------------
__global__ void k_detect(const int* __restrict__ ei32) {
    int t = threadIdx.x;              // 256 threads, 1 block
    int nz = 0;
    #pragma unroll
    for (int i = t; i < 4096; i += 256) nz |= ei32[2 * i + 1];
    int any = __syncthreads_or(nz != 0);
    if (t == 0) g_is64 = any ? 0 : 1;
}

// ---------------------------------------------------------------------------
// 1) zero the bitmask
// ---------------------------------------------------------------------------
__global__ void k_zero_mask() {
    int i = blockIdx.x * blockDim.x + threadIdx.x;
    if (i < N_NODES * MW) g_mask[i] = 0u;
}

// ---------------------------------------------------------------------------
// 2) scatter edges symmetrically into the bitmask (dedup for free).
//    Handles both int32 and int64 edge_index via g_is64. Indices masked to
//    [0,8191] defensively (no-op for valid data).
// ---------------------------------------------------------------------------
__global__ void k_scatter(const void* __restrict__ ei_raw) {
    int e = blockIdx.x * blockDim.x + threadIdx.x;
    if (e >= N_EDGES) return;
    int u, v;
    if (g_is64) {
        const long long* ei = (const long long*)ei_raw;
        u = (int)ei[e];
        v = (int)ei[N_EDGES + e];
    } else {
        const int* ei = (const int*)ei_raw;
        u = ei[e];
        v = ei[N_EDGES + e];
    }
    u &= (N_NODES - 1);
    v &= (N_NODES - 1);
    atomicOr(&g_mask[u * MW + (v >> 5)], 1u << (v & 31));
    atomicOr(&g_mask[v * MW + (u >> 5)], 1u << (u & 31));
}

// ---------------------------------------------------------------------------
// 3) degree + dinv: one warp per row, coalesced popcount.
//    deg = popcount(row) + 1  (the +1 is the added identity; a self-edge bit
//    already present correctly makes the diagonal weight 2)
// ---------------------------------------------------------------------------
__global__ void k_degree() {
    int row  = blockIdx.x * (blockDim.x >> 5) + (threadIdx.x >> 5);
    int lane = threadIdx.x & 31;
    if (row >= N_NODES) return;
    const unsigned int* m = &g_mask[row * MW];
    int cnt = 0;
    #pragma unroll
    for (int w = 0; w < MW / 32; w++) cnt += __popc(m[lane + w * 32]);
    #pragma unroll
    for (int o = 16; o; o >>= 1) cnt += __shfl_xor_sync(0xffffffffu, cnt, o);
    if (lane == 0) g_dinv[row] = rsqrtf((float)(cnt + 1));
}

// ---------------------------------------------------------------------------
// 4) GEMM: H'[m][n] = dinv[m] * sum_k X[m][k] * W[k][n]
//    128x64 tile, BK=16, 256 threads, 8x4 per-thread microtile (fp32)
// ---------------------------------------------------------------------------
#define BM 128
#define BN 64
#define BK 16
#define TM 8
#define TN 4

__global__ __launch_bounds__(256) void k_gemm(const float* __restrict__ X,
                                              const float* __restrict__ W) {
    __shared__ float Xs[BM][BK];
    __shared__ float Ws[BK][BN];

    int tid = threadIdx.x;            // 0..255
    int tx  = tid & 15;               // 16 col groups
    int ty  = tid >> 4;               // 16 row groups
    int rowBase = blockIdx.y * BM;
    int colBase = blockIdx.x * BN;

    float acc[TM][TN];
    #pragma unroll
    for (int m = 0; m < TM; m++)
        #pragma unroll
        for (int n = 0; n < TN; n++) acc[m][n] = 0.0f;

    for (int kt = 0; kt < D; kt += BK) {
        #pragma unroll
        for (int i = 0; i < 8; i++) {
            int e = tid + i * 256;
            int r = e >> 4, c = e & 15;
            Xs[r][c] = X[(rowBase + r) * D + kt + c];
        }
        #pragma unroll
        for (int i = 0; i < 4; i++) {
            int e = tid + i * 256;
            int r = e >> 6, c = e & 63;
            Ws[r][c] = W[(kt + r) * D + colBase + c];
        }
        __syncthreads();

        #pragma unroll
        for (int k = 0; k < BK; k++) {
            float xr[TM], wr[TN];
            #pragma unroll
            for (int m = 0; m < TM; m++) xr[m] = Xs[ty * TM + m][k];
            #pragma unroll
            for (int n = 0; n < TN; n++) wr[n] = Ws[k][tx * TN + n];
            #pragma unroll
            for (int m = 0; m < TM; m++)
                #pragma unroll
                for (int n = 0; n < TN; n++)
                    acc[m][n] += xr[m] * wr[n];
        }
        __syncthreads();
    }

    #pragma unroll
    for (int m = 0; m < TM; m++) {
        int row = rowBase + ty * TM + m;
        float s = g_dinv[row];
        #pragma unroll
        for (int n = 0; n < TN; n++)
            g_h[row * D + colBase + tx * TN + n] = s * acc[m][n];
    }
}

// ---------------------------------------------------------------------------
// 5) SpMM gather: out[i] = dinv[i] * (sum_{j in mask row i} H'[j] + H'[i]) + b
//    one block per node; 128 threads each own a float4 (512 floats / row).
//    H' is 16 MB so neighbor-row gathers stay L2-resident.
// ---------------------------------------------------------------------------
__global__ __launch_bounds__(128) void k_spmm(const float* __restrict__ bias,
                                              float* __restrict__ out) {
    __shared__ unsigned int smask[MW];
    int row = blockIdx.x;
    int tid = threadIdx.x;            // 0..127

    smask[tid]       = g_mask[row * MW + tid];
    smask[tid + 128] = g_mask[row * MW + tid + 128];
    __syncthreads();

    const float4* H4 = (const float4*)g_h;

    // identity term (+I): start with own row
    float4 acc = H4[row * (D / 4) + tid];

    for (int w = 0; w < MW; w++) {
        unsigned int bits = smask[w];
        while (bits) {
            int b = __ffs(bits) - 1;
            bits &= bits - 1;
            int j = (w << 5) + b;
            float4 v = H4[j * (D / 4) + tid];
            acc.x += v.x; acc.y += v.y; acc.z += v.z; acc.w += v.w;
        }
    }

    float s   = g_dinv[row];
    float4 bb = ((const float4*)bias)[tid];
    float4 o;
    o.x = s * acc.x + bb.x;
    o.y = s * acc.y + bb.y;
    o.z = s * acc.z + bb.z;
    o.w = s * acc.w + bb.w;
    ((float4*)out)[row * (D / 4) + tid] = o;
}

// ---------------------------------------------------------------------------
// launch
// inputs (metadata order): x [8192,512] f32, edge_index [2,262144] int,
//                          weight [512,512] f32, bias [512] f32
// output: [8192,512] f32
// ---------------------------------------------------------------------------
extern "C" void kernel_launch(void* const* d_in, const int* in_sizes, int n_in,
                              void* d_out, int out_size) {
    const float* x    = (const float*)d_in[0];
    const void*  ei   = d_in[1];
    const float* w    = (const float*)d_in[2];
    const float* bias = (const float*)d_in[3];
    float*       out  = (float*)d_out;

    k_detect<<<1, 256>>>((const int*)ei);
    k_zero_mask<<<(N_NODES * MW + 255) / 256, 256>>>();
    k_scatter<<<(N_EDGES + 255) / 256, 256>>>(ei);
    k_degree<<<N_NODES / 8, 256>>>();

    dim3 gemmGrid(D / BN, N_NODES / BM);
    k_gemm<<<gemmGrid, 256>>>(x, w);

    k_spmm<<<N_NODES, 128>>>(bias, out);
}

// round 3
// speedup vs baseline: 1.9720x; 1.9720x over previous
#include <cuda_runtime.h>
#include <cuda_bf16.h>
#include <cstdint>

#define N_NODES 8192
#define N_EDGES 262144
#define D 512
#define MW 256   // 8192 bits / 32 = 256 mask words per row

// Scratch (device globals; no allocations allowed)
__device__ unsigned int g_mask[N_NODES * MW];                    // 8 MB adjacency bitmask
__device__ float        g_dinv[N_NODES];                         // D^{-1/2}
__device__ __align__(16) float g_h[N_NODES * D];                 // H' = dinv*(X@W)
__device__ int          g_is64;                                  // edge_index dtype flag
__device__ __align__(16) __nv_bfloat16 g_xhi[N_NODES * D];       // bf16 split of X
__device__ __align__(16) __nv_bfloat16 g_xlo[N_NODES * D];
__device__ __align__(16) __nv_bfloat16 g_whi[D * D];             // bf16 split of W
__device__ __align__(16) __nv_bfloat16 g_wlo[D * D];

// ---------------------------------------------------------------------------
// 0) detect edge_index dtype (int64 vs int32)
// ---------------------------------------------------------------------------
__global__ void k_detect(const int* __restrict__ ei32) {
    int t = threadIdx.x;
    int nz = 0;
    #pragma unroll
    for (int i = t; i < 4096; i += 256) nz |= ei32[2 * i + 1];
    int any = __syncthreads_or(nz != 0);
    if (t == 0) g_is64 = any ? 0 : 1;
}

// ---------------------------------------------------------------------------
// 1) zero bitmask (vectorized)
// ---------------------------------------------------------------------------
__global__ void k_zero_mask() {
    int i = blockIdx.x * blockDim.x + threadIdx.x;
    if (i < N_NODES * MW / 4) ((uint4*)g_mask)[i] = make_uint4(0, 0, 0, 0);
}

// ---------------------------------------------------------------------------
// 2) symmetric edge scatter into bitmask (dedup for free)
// ---------------------------------------------------------------------------
__global__ void k_scatter(const void* __restrict__ ei_raw) {
    int e = blockIdx.x * blockDim.x + threadIdx.x;
    if (e >= N_EDGES) return;
    int u, v;
    if (g_is64) {
        const long long* ei = (const long long*)ei_raw;
        u = (int)ei[e];
        v = (int)ei[N_EDGES + e];
    } else {
        const int* ei = (const int*)ei_raw;
        u = ei[e];
        v = ei[N_EDGES + e];
    }
    u &= (N_NODES - 1);
    v &= (N_NODES - 1);
    atomicOr(&g_mask[u * MW + (v >> 5)], 1u << (v & 31));
    atomicOr(&g_mask[v * MW + (u >> 5)], 1u << (u & 31));
}

// ---------------------------------------------------------------------------
// 3) degree + dinv: one warp per row.  deg = popcount + 1 (identity)
// ---------------------------------------------------------------------------
__global__ void k_degree() {
    int row  = blockIdx.x * (blockDim.x >> 5) + (threadIdx.x >> 5);
    int lane = threadIdx.x & 31;
    if (row >= N_NODES) return;
    const unsigned int* m = &g_mask[row * MW];
    int cnt = 0;
    #pragma unroll
    for (int w = 0; w < MW / 32; w++) cnt += __popc(m[lane + w * 32]);
    #pragma unroll
    for (int o = 16; o; o >>= 1) cnt += __shfl_xor_sync(0xffffffffu, cnt, o);
    if (lane == 0) g_dinv[row] = rsqrtf((float)(cnt + 1));
}

// ---------------------------------------------------------------------------
// 3b) split fp32 -> bf16 hi + bf16 lo  (x = hi + lo + O(2^-16 x))
// ---------------------------------------------------------------------------
__global__ void k_split4(const float4* __restrict__ src,
                         __nv_bfloat162* __restrict__ hi,
                         __nv_bfloat162* __restrict__ lo, int n4) {
    int i = blockIdx.x * blockDim.x + threadIdx.x;
    if (i >= n4) return;
    float4 v = src[i];
    __nv_bfloat16 hx = __float2bfloat16_rn(v.x);
    __nv_bfloat16 hy = __float2bfloat16_rn(v.y);
    __nv_bfloat16 hz = __float2bfloat16_rn(v.z);
    __nv_bfloat16 hw = __float2bfloat16_rn(v.w);
    hi[2 * i]     = __nv_bfloat162(hx, hy);
    hi[2 * i + 1] = __nv_bfloat162(hz, hw);
    lo[2 * i]     = __nv_bfloat162(__float2bfloat16_rn(v.x - __bfloat162float(hx)),
                                   __float2bfloat16_rn(v.y - __bfloat162float(hy)));
    lo[2 * i + 1] = __nv_bfloat162(__float2bfloat16_rn(v.z - __bfloat162float(hz)),
                                   __float2bfloat16_rn(v.w - __bfloat162float(hw)));
}

// ---------------------------------------------------------------------------
// 4) Tensor-core GEMM with bf16 hi/lo split (3 mma passes, fp32 acc):
//    H'[m][n] = dinv[m] * sum_k X[m][k]*W[k][n]
//    128x128 block tile, BK=32, 8 warps (2x4), 64x32 warp tile, m16n8k16 mma
// ---------------------------------------------------------------------------
#define GBM 128
#define GBN 128
#define GBK 32
#define ASTRIDE 40   // 32 + 8 pad (bf16) -> conflict-free ldmatrix
#define BSTRIDE 144  // 128 + 16 pad

__device__ __forceinline__ void ldsm_x4(uint32_t* r, const void* p) {
    uint32_t a = (uint32_t)__cvta_generic_to_shared(p);
    asm volatile("ldmatrix.sync.aligned.m8n8.x4.shared.b16 {%0,%1,%2,%3}, [%4];"
                 : "=r"(r[0]), "=r"(r[1]), "=r"(r[2]), "=r"(r[3]) : "r"(a));
}
__device__ __forceinline__ void ldsm_x4t(uint32_t* r, const void* p) {
    uint32_t a = (uint32_t)__cvta_generic_to_shared(p);
    asm volatile("ldmatrix.sync.aligned.m8n8.x4.trans.shared.b16 {%0,%1,%2,%3}, [%4];"
                 : "=r"(r[0]), "=r"(r[1]), "=r"(r[2]), "=r"(r[3]) : "r"(a));
}
__device__ __forceinline__ void mma16816(float* c, const uint32_t* a, const uint32_t* b) {
    asm volatile("mma.sync.aligned.m16n8k16.row.col.f32.bf16.bf16.f32 "
                 "{%0,%1,%2,%3}, {%4,%5,%6,%7}, {%8,%9}, {%0,%1,%2,%3};"
                 : "+f"(c[0]), "+f"(c[1]), "+f"(c[2]), "+f"(c[3])
                 : "r"(a[0]), "r"(a[1]), "r"(a[2]), "r"(a[3]), "r"(b[0]), "r"(b[1]));
}

__global__ __launch_bounds__(256) void k_gemm_mma() {
    __shared__ __nv_bfloat16 Ah[GBM * ASTRIDE], Al[GBM * ASTRIDE];
    __shared__ __nv_bfloat16 Bh[GBK * BSTRIDE], Bl[GBK * BSTRIDE];

    int tid  = threadIdx.x;
    int lane = tid & 31;
    int wid  = tid >> 5;
    int wm   = wid & 1;          // 0..1 -> rows wm*64
    int wn   = wid >> 1;         // 0..3 -> cols wn*32
    int rowBase = blockIdx.y * GBM;
    int colBase = blockIdx.x * GBN;

    // per-thread load coords
    int ar = tid >> 2, ac = (tid & 3) * 8;     // A: 64 rows/pass, 2 passes
    int br = tid >> 4, bc = (tid & 15) * 8;    // B: 16 rows/pass, 2 passes

    float acc[4][4][4];
    #pragma unroll
    for (int mi = 0; mi < 4; mi++)
        #pragma unroll
        for (int ni = 0; ni < 4; ni++)
            #pragma unroll
            for (int q = 0; q < 4; q++) acc[mi][ni][q] = 0.0f;

    uint4 pAh[2], pAl[2], pBh[2], pBl[2];
    // preload k-tile 0
    #pragma unroll
    for (int p = 0; p < 2; p++) {
        pAh[p] = *(const uint4*)&g_xhi[(rowBase + ar + p * 64) * D + ac];
        pAl[p] = *(const uint4*)&g_xlo[(rowBase + ar + p * 64) * D + ac];
        pBh[p] = *(const uint4*)&g_whi[(br + p * 16) * D + colBase + bc];
        pBl[p] = *(const uint4*)&g_wlo[(br + p * 16) * D + colBase + bc];
    }

    for (int kt = 0; kt < D; kt += GBK) {
        __syncthreads();   // previous mma done reading smem
        #pragma unroll
        for (int p = 0; p < 2; p++) {
            *(uint4*)&Ah[(ar + p * 64) * ASTRIDE + ac] = pAh[p];
            *(uint4*)&Al[(ar + p * 64) * ASTRIDE + ac] = pAl[p];
            *(uint4*)&Bh[(br + p * 16) * BSTRIDE + bc] = pBh[p];
            *(uint4*)&Bl[(br + p * 16) * BSTRIDE + bc] = pBl[p];
        }
        __syncthreads();

        if (kt + GBK < D) {
            int kn = kt + GBK;
            #pragma unroll
            for (int p = 0; p < 2; p++) {
                pAh[p] = *(const uint4*)&g_xhi[(rowBase + ar + p * 64) * D + kn + ac];
                pAl[p] = *(const uint4*)&g_xlo[(rowBase + ar + p * 64) * D + kn + ac];
                pBh[p] = *(const uint4*)&g_whi[(kn + br + p * 16) * D + colBase + bc];
                pBl[p] = *(const uint4*)&g_wlo[(kn + br + p * 16) * D + colBase + bc];
            }
        }

        #pragma unroll
        for (int kk = 0; kk < GBK; kk += 16) {
            uint32_t afh[4][4], afl[4][4];
            #pragma unroll
            for (int mi = 0; mi < 4; mi++) {
                int r = wm * 64 + mi * 16 + (lane & 15);
                int c = kk + ((lane >> 4) << 3);
                ldsm_x4(afh[mi], &Ah[r * ASTRIDE + c]);
                ldsm_x4(afl[mi], &Al[r * ASTRIDE + c]);
            }
            uint32_t bfh[4][2], bfl[4][2];
            #pragma unroll
            for (int np = 0; np < 2; np++) {
                int r = kk + (lane & 15);
                int c = wn * 32 + np * 16 + ((lane >> 4) << 3);
                uint32_t t4[4];
                ldsm_x4t(t4, &Bh[r * BSTRIDE + c]);
                bfh[2 * np][0] = t4[0]; bfh[2 * np][1] = t4[1];
                bfh[2 * np + 1][0] = t4[2]; bfh[2 * np + 1][1] = t4[3];
                ldsm_x4t(t4, &Bl[r * BSTRIDE + c]);
                bfl[2 * np][0] = t4[0]; bfl[2 * np][1] = t4[1];
                bfl[2 * np + 1][0] = t4[2]; bfl[2 * np + 1][1] = t4[3];
            }
            #pragma unroll
            for (int mi = 0; mi < 4; mi++)
                #pragma unroll
                for (int ni = 0; ni < 4; ni++) {
                    mma16816(acc[mi][ni], afh[mi], bfh[ni]);   // hi*hi
                    mma16816(acc[mi][ni], afh[mi], bfl[ni]);   // hi*lo
                    mma16816(acc[mi][ni], afl[mi], bfh[ni]);   // lo*hi
                }
        }
    }

    // epilogue: scale by dinv[row], write fp32 H'
    int g  = lane >> 2;
    int tg = lane & 3;
    #pragma unroll
    for (int mi = 0; mi < 4; mi++) {
        int row0 = rowBase + wm * 64 + mi * 16 + g;
        int row1 = row0 + 8;
        float s0 = g_dinv[row0], s1 = g_dinv[row1];
        #pragma unroll
        for (int ni = 0; ni < 4; ni++) {
            int col = colBase + wn * 32 + ni * 8 + tg * 2;
            float2 v0 = make_float2(s0 * acc[mi][ni][0], s0 * acc[mi][ni][1]);
            float2 v1 = make_float2(s1 * acc[mi][ni][2], s1 * acc[mi][ni][3]);
            *(float2*)&g_h[row0 * D + col] = v0;
            *(float2*)&g_h[row1 * D + col] = v1;
        }
    }
}

// ---------------------------------------------------------------------------
// 5) SpMM gather: out[i] = dinv[i] * (sum_{j in row i} H'[j] + H'[i]) + bias
//    Decode bitmask -> smem index list (deterministic scan), then stride-4
//    unrolled gather with 4 independent accumulators (MLP >= 4).
// ---------------------------------------------------------------------------
#define LIST_CAP 4096

__global__ __launch_bounds__(128) void k_spmm(const float* __restrict__ bias,
                                              float* __restrict__ out) {
    __shared__ unsigned int smask[MW];
    __shared__ unsigned short list[LIST_CAP];
    __shared__ int wsum[4];

    int row  = blockIdx.x;
    int tid  = threadIdx.x;
    int lane = tid & 31;
    int wrp  = tid >> 5;

    smask[tid]       = g_mask[row * MW + tid];
    smask[tid + 128] = g_mask[row * MW + tid + 128];
    __syncthreads();

    // counts + deterministic block scan
    unsigned int w0 = smask[2 * tid], w1 = smask[2 * tid + 1];
    int c = __popc(w0) + __popc(w1);
    int p = c;
    #pragma unroll
    for (int o = 1; o < 32; o <<= 1) {
        int t = __shfl_up_sync(0xffffffffu, p, o);
        if (lane >= o) p += t;
    }
    if (lane == 31) wsum[wrp] = p;
    __syncthreads();
    int wbase = 0;
    #pragma unroll
    for (int w = 0; w < 4; w++) wbase += (w < wrp) ? wsum[w] : 0;
    int total = wsum[0] + wsum[1] + wsum[2] + wsum[3];

    const float4* H4 = (const float4*)g_h;
    float4 acc0 = H4[row * (D / 4) + tid];                 // identity term
    float4 acc1 = make_float4(0, 0, 0, 0);
    float4 acc2 = make_float4(0, 0, 0, 0);
    float4 acc3 = make_float4(0, 0, 0, 0);

    if (total <= LIST_CAP) {
        int off = wbase + p - c;  // exclusive prefix
        unsigned int bits = w0;
        int base = (2 * tid) << 5;
        while (bits) { int b = __ffs(bits) - 1; bits &= bits - 1; list[off++] = (unsigned short)(base + b); }
        bits = w1; base = (2 * tid + 1) << 5;
        while (bits) { int b = __ffs(bits) - 1; bits &= bits - 1; list[off++] = (unsigned short)(base + b); }
        __syncthreads();

        int i = 0;
        for (; i + 4 <= total; i += 4) {
            int j0 = list[i], j1 = list[i + 1], j2 = list[i + 2], j3 = list[i + 3];
            float4 v0 = H4[j0 * (D / 4) + tid];
            float4 v1 = H4[j1 * (D / 4) + tid];
            float4 v2 = H4[j2 * (D / 4) + tid];
            float4 v3 = H4[j3 * (D / 4) + tid];
            acc0.x += v0.x; acc0.y += v0.y; acc0.z += v0.z; acc0.w += v0.w;
            acc1.x += v1.x; acc1.y += v1.y; acc1.z += v1.z; acc1.w += v1.w;
            acc2.x += v2.x; acc2.y += v2.y; acc2.z += v2.z; acc2.w += v2.w;
            acc3.x += v3.x; acc3.y += v3.y; acc3.z += v3.z; acc3.w += v3.w;
        }
        for (; i < total; i++) {
            float4 v = H4[list[i] * (D / 4) + tid];
            acc0.x += v.x; acc0.y += v.y; acc0.z += v.z; acc0.w += v.w;
        }
    } else {
        // fallback: direct bit-walk (degenerate graphs)
        for (int w = 0; w < MW; w++) {
            unsigned int bits = smask[w];
            while (bits) {
                int b = __ffs(bits) - 1;
                bits &= bits - 1;
                float4 v = H4[((w << 5) + b) * (D / 4) + tid];
                acc0.x += v.x; acc0.y += v.y; acc0.z += v.z; acc0.w += v.w;
            }
        }
    }

    acc0.x += acc1.x + acc2.x + acc3.x;
    acc0.y += acc1.y + acc2.y + acc3.y;
    acc0.z += acc1.z + acc2.z + acc3.z;
    acc0.w += acc1.w + acc2.w + acc3.w;

    float s   = g_dinv[row];
    float4 bb = ((const float4*)bias)[tid];
    float4 o;
    o.x = s * acc0.x + bb.x;
    o.y = s * acc0.y + bb.y;
    o.z = s * acc0.z + bb.z;
    o.w = s * acc0.w + bb.w;
    ((float4*)out)[row * (D / 4) + tid] = o;
}

// ---------------------------------------------------------------------------
// launch
// ---------------------------------------------------------------------------
extern "C" void kernel_launch(void* const* d_in, const int* in_sizes, int n_in,
                              void* d_out, int out_size) {
    const float* x    = (const float*)d_in[0];
    const void*  ei   = d_in[1];
    const float* w    = (const float*)d_in[2];
    const float* bias = (const float*)d_in[3];
    float*       out  = (float*)d_out;

    k_detect<<<1, 256>>>((const int*)ei);
    k_zero_mask<<<(N_NODES * MW / 4 + 255) / 256, 256>>>();
    k_scatter<<<(N_EDGES + 255) / 256, 256>>>(ei);
    k_degree<<<N_NODES / 8, 256>>>();

    __nv_bfloat162 *xhi, *xlo, *whi, *wlo;
    cudaGetSymbolAddress((void**)&xhi, g_xhi);
    cudaGetSymbolAddress((void**)&xlo, g_xlo);
    cudaGetSymbolAddress((void**)&whi, g_whi);
    cudaGetSymbolAddress((void**)&wlo, g_wlo);

    int nx4 = N_NODES * D / 4;
    int nw4 = D * D / 4;
    k_split4<<<(nx4 + 255) / 256, 256>>>((const float4*)x, xhi, xlo, nx4);
    k_split4<<<(nw4 + 255) / 256, 256>>>((const float4*)w, whi, wlo, nw4);

    dim3 gemmGrid(D / GBN, N_NODES / GBM);
    k_gemm_mma<<<gemmGrid, 256>>>();

    k_spmm<<<N_NODES, 128>>>(bias, out);
}